// round 12
// baseline (speedup 1.0000x reference)
#include <cuda_runtime.h>
#include <math.h>

#define BATCH 4
#define NPTS 8192
#define NS   2048
#define KS   32
#define DD   64
#define CO   128
#define NC   (BATCH*NS)          // 8192 centers
#define NELEM (NC*KS)            // 262144
#define FULLM 0xffffffffu

typedef unsigned long long u64;

// packed f32x2 helpers — each half is a bit-exact scalar .rn op (PTX ISA 8.6, sm_100+)
#define PK2(out, lo, hi) asm("mov.b64 %0, {%1, %2};" : "=l"(out) : "r"(__float_as_uint(lo)), "r"(__float_as_uint(hi)))
#define UPK2(lo, hi, in) do { unsigned _a,_b; asm("mov.b64 {%0, %1}, %2;" : "=r"(_a), "=r"(_b) : "l"(in)); lo=__uint_as_float(_a); hi=__uint_as_float(_b); } while(0)
#define ADD2(o, a, b) asm("add.rn.f32x2 %0, %1, %2;" : "=l"(o) : "l"(a), "l"(b))
#define MUL2(o, a, b) asm("mul.rn.f32x2 %0, %1, %2;" : "=l"(o) : "l"(a), "l"(b))
#define FMA2(acc, a, b) asm("fma.rn.f32x2 %0, %1, %2, %0;" : "+l"(acc) : "l"(a), "l"(b))

// ------------------- device scratch (no runtime allocation) -------------------
__device__ float  g_newxyz[NC*3];
__device__ int    g_gidx[NC*KS];
__device__ float  g_gm[NC*3*KS];          // [c][coord][k]
__device__ float  g_dsv[NC*KS];
__device__ float  g_tbuf[NC*KS];
__device__ double g_part1[1024*11];
__device__ double g_part2[1024];
__device__ float  g_cst[128];             // 0..31 scW, 32..63 shW, 64..79 A, 80..95 B, 96 S2, 97 T2
__device__ float  g_ptsT[(size_t)BATCH*NPTS*DD];     // 8 MB
__device__ float  g_mixed[(size_t)NC*2048];          // 64 MB
__device__ float  g_Y[(size_t)NC*CO];                // 4 MB
__device__ double g_ypart[256*256];
__device__ float  g_ysc[256];

// ---------------- dummies: shift fps_kernel into the ncu profiled slot ----------------
__global__ void dummy_kernel() {}

// ---------------- K0: transpose points (B,64,N) -> (B,N,64) ----------------
__global__ void transpose_kernel(const float* __restrict__ points) {
    __shared__ float tile[32][33];
    int b = blockIdx.z;
    int i0 = blockIdx.x * 32, d0 = blockIdx.y * 32;
    int tx = threadIdx.x, ty = threadIdx.y;   // 32 x 8
    const float* pb = points + (size_t)b * DD * NPTS;
    float* ob = g_ptsT + (size_t)b * NPTS * DD;
#pragma unroll
    for (int k = 0; k < 4; k++)
        tile[ty + k*8][tx] = pb[(size_t)(d0 + ty + k*8) * NPTS + i0 + tx];
    __syncthreads();
#pragma unroll
    for (int k = 0; k < 4; k++)
        ob[(size_t)(i0 + ty + k*8) * DD + d0 + tx] = tile[tx][ty + k*8];
}

// ---------------- K1: farthest point sampling (1 CTA / batch, 512 threads) ----------------
// 512 threads x 16 points/thread: same total fma work (pipe floor unchanged)
// but 4 warps/SMSP instead of 2 — doubles latency-hiding slack on the
// dependent distance chains; rescan halves to 15 compares. Reduction:
// redux.sync.max.u32 on float bits per warp, redundant block max over 16 smem
// warp maxima, rescan + atomicMin only for block-max-matching threads.
// First-occurrence argmax semantics and trajectory bit-identical.
__global__ __launch_bounds__(512, 1) void fps_kernel(const float* __restrict__ xyz) {
    extern __shared__ float sm[];
    float* sx = sm;
    float* sy = sm + NPTS;
    float* sz = sm + 2*NPTS;
    __shared__ float wv[16];
    __shared__ int   sbest[2];
    int b = blockIdx.x;
    const float* xb = xyz + (size_t)b * 3 * NPTS;
    int t = threadIdx.x;
    int lane = t & 31, warp = t >> 5;
    int base = t * 16;
    u64 pxp[8], pyp[8], pzp[8];
    float dmin[16];
#pragma unroll
    for (int i = 0; i < 8; i++) {
        float x0 = xb[base + 2*i],          x1 = xb[base + 2*i + 1];
        float y0 = xb[NPTS + base + 2*i],   y1 = xb[NPTS + base + 2*i + 1];
        float z0 = xb[2*NPTS + base + 2*i], z1 = xb[2*NPTS + base + 2*i + 1];
        PK2(pxp[i], x0, x1); PK2(pyp[i], y0, y1); PK2(pzp[i], z0, z1);
        sx[base + 2*i] = x0; sx[base + 2*i + 1] = x1;
        sy[base + 2*i] = y0; sy[base + 2*i + 1] = y1;
        sz[base + 2*i] = z0; sz[base + 2*i + 1] = z1;
        dmin[2*i] = 10000000000.0f; dmin[2*i + 1] = 10000000000.0f;
    }
    if (t == 0) sbest[0] = 0;
    __syncthreads();
    float* outp = g_newxyz + (size_t)b * NS * 3;
    for (int s = 0; s < NS; s++) {
        int cur = sbest[s & 1];
        float cx = sx[cur], cy = sy[cur], cz = sz[cur];
        if (t == 0) {
            outp[s*3] = cx; outp[s*3+1] = cy; outp[s*3+2] = cz;
            sbest[(s + 1) & 1] = 0x7fffffff;   // reset next-step slot (pre-BAR1)
        }
        u64 ncx, ncy, ncz;
        PK2(ncx, -cx, -cx); PK2(ncy, -cy, -cy); PK2(ncz, -cz, -cz);
        float v = -1.0f;
#pragma unroll
        for (int i = 0; i < 8; i++) {
            u64 dx, dy, dz, xx, yy, zz, ss, dd;
            ADD2(dx, pxp[i], ncx);      // px + (-cx)  == px - cx exactly
            ADD2(dy, pyp[i], ncy);
            ADD2(dz, pzp[i], ncz);
            MUL2(xx, dx, dx);
            MUL2(yy, dy, dy);
            MUL2(zz, dz, dz);
            ADD2(ss, xx, yy);
            ADD2(dd, ss, zz);
            float d0, d1; UPK2(d0, d1, dd);
            float m0 = fminf(dmin[2*i],     d0); dmin[2*i]     = m0;
            float m1 = fminf(dmin[2*i + 1], d1); dmin[2*i + 1] = m1;
            v = fmaxf(v, fmaxf(m0, m1));
        }
        // warp max on bits (v >= 0 so the bit pattern is monotone in value)
        unsigned vbits = __float_as_uint(v);
        unsigned wbits;
        asm("redux.sync.max.u32 %0, %1, 0xffffffff;" : "=r"(wbits) : "r"(vbits));
        if (lane == 0) wv[warp] = __uint_as_float(wbits);
        __syncthreads();                       // BAR1: wv ready, reset visible
        float vblk = fmaxf(
            fmaxf(fmaxf(fmaxf(wv[0], wv[1]), fmaxf(wv[2], wv[3])),
                  fmaxf(fmaxf(wv[4], wv[5]), fmaxf(wv[6], wv[7]))),
            fmaxf(fmaxf(fmaxf(wv[8], wv[9]), fmaxf(wv[10], wv[11])),
                  fmaxf(fmaxf(wv[12], wv[13]), fmaxf(wv[14], wv[15]))));
        if (v == vblk) {                       // ~1 thread per block
            int cand = base + 15;
#pragma unroll
            for (int j = 14; j >= 0; j--) if (dmin[j] == vblk) cand = base + j;
            atomicMin(&sbest[(s + 1) & 1], cand);
        }
        __syncthreads();                       // BAR2: sbest final
    }
}

// ------- K2: query ball + grouping + density + ds + moment partials -------
__global__ __launch_bounds__(256) void qball_kernel(const float* __restrict__ xyz,
                                                    const float* __restrict__ radius) {
    int warp = threadIdx.x >> 5, lane = threadIdx.x & 31;
    int c = blockIdx.x * 8 + warp;
    int b = c >> 11;
    __shared__ int   sidx[8][KS];
    __shared__ float sred[8][11];
    const float* xb = xyz + (size_t)b * 3 * NPTS;
    float cx = g_newxyz[c*3], cy = g_newxyz[c*3+1], cz = g_newxyz[c*3+2];
    float cn2 = __fadd_rn(__fadd_rn(__fmul_rn(cx,cx), __fmul_rn(cy,cy)), __fmul_rn(cz,cz));
    float r = radius[0];
    float r2 = __fmul_rn(r, r);
    int cnt = 0;
    for (int nb = 0; nb < NPTS; nb += 32) {
        int i = nb + lane;
        float x = xb[i], y = xb[NPTS + i], z = xb[2*NPTS + i];
        float pn2 = __fadd_rn(__fadd_rn(__fmul_rn(x,x), __fmul_rn(y,y)), __fmul_rn(z,z));
        float dot = fmaf(cz, z, fmaf(cy, y, __fmul_rn(cx, x)));
        float sq  = __fsub_rn(__fadd_rn(cn2, pn2), __fmul_rn(2.0f, dot));
        bool in = !(sq > r2);
        unsigned msk = __ballot_sync(FULLM, in);
        if (in) {
            int pos = cnt + __popc(msk & ((1u << lane) - 1u));
            if (pos < KS) sidx[warp][pos] = i;
        }
        cnt += __popc(msk);
        if (cnt >= KS) break;
    }
    __syncwarp();
    int first = sidx[warp][0];
    __syncwarp();
    if (lane >= cnt) sidx[warp][lane] = first;
    __syncwarp();
    int gi = sidx[warp][lane];
    float gx, gy, gz;
    if (lane == 0) { gx = 0.f; gy = 0.f; gz = 0.f; }
    else { gx = xb[gi]; gy = xb[NPTS + gi]; gz = xb[2*NPTS + gi]; }
    float den = __fadd_rn(__fadd_rn(gx, gy), gz);
    if (den < 1e-10f) den = 1e-10f;
    float inv = 1.0f / den;
    float mx = inv;
#pragma unroll
    for (int o = 16; o > 0; o >>= 1) mx = fmaxf(mx, __shfl_xor_sync(FULLM, mx, o));
    float dsv = inv / mx;
    g_gidx[c*KS + lane] = gi;
    g_gm[(size_t)(c*3 + 0)*KS + lane] = gx;
    g_gm[(size_t)(c*3 + 1)*KS + lane] = gy;
    g_gm[(size_t)(c*3 + 2)*KS + lane] = gz;
    g_dsv[c*KS + lane] = dsv;
    float q[11] = {gx, gy, gz, gx*gx, gx*gy, gx*gz, gy*gy, gy*gz, gz*gz, dsv, dsv*dsv};
#pragma unroll
    for (int qi = 0; qi < 11; qi++) {
        float vv = q[qi];
#pragma unroll
        for (int o = 16; o > 0; o >>= 1) vv += __shfl_xor_sync(FULLM, vv, o);
        if (lane == 0) sred[warp][qi] = vv;
    }
    __syncthreads();
    if (threadIdx.x < 11) {
        double ssum = 0.0;
#pragma unroll
        for (int w = 0; w < 8; w++) ssum += (double)sred[w][threadIdx.x];
        g_part1[blockIdx.x * 11 + threadIdx.x] = ssum;
    }
}

// ---------------- K3: finalize BN(w) and BN(n1) constants (warp-parallel) ----------------
__global__ void finalize1_kernel(const float* __restrict__ W_h, const float* __restrict__ b_h,
                                 const float* __restrict__ g_h, const float* __restrict__ be_h,
                                 const float* __restrict__ W_n1, const float* __restrict__ b_n1,
                                 const float* __restrict__ g_n1, const float* __restrict__ be_n1) {
    __shared__ double S[11];
    int t = threadIdx.x;          // 384 threads, 12 warps
    int warp = t >> 5, lane = t & 31;
    if (warp < 11) {
        double s = 0.0;
        for (int i = lane; i < 1024; i += 32) s += g_part1[i*11 + warp];
#pragma unroll
        for (int o = 16; o > 0; o >>= 1) s += __shfl_down_sync(FULLM, s, o);
        if (lane == 0) S[warp] = s;
    }
    __syncthreads();
    const double n = (double)NELEM;
    if (t < 32) {
        double mux = S[0]/n, muy = S[1]/n, muz = S[2]/n;
        double cxx = S[3]/n - mux*mux, cxy = S[4]/n - mux*muy, cxz = S[5]/n - mux*muz;
        double cyy = S[6]/n - muy*muy, cyz = S[7]/n - muy*muz, czz = S[8]/n - muz*muz;
        double w0 = W_h[t*3], w1 = W_h[t*3+1], w2 = W_h[t*3+2];
        double mua = w0*mux + w1*muy + w2*muz + (double)b_h[t];
        double var = w0*w0*cxx + w1*w1*cyy + w2*w2*czz
                   + 2.0*(w0*w1*cxy + w0*w2*cxz + w1*w2*cyz);
        double sc = (double)g_h[t] / sqrt(var + 1e-5);
        g_cst[t]      = (float)sc;
        g_cst[32 + t] = (float)((double)be_h[t] - mua * sc);
    }
    if (t < 16) {
        double mud  = S[9]/n;
        double vard = S[10]/n - mud*mud;
        double w = W_n1[t];
        double muz2 = w*mud + (double)b_n1[t];
        double varz = w*w*vard;
        double scz = (double)g_n1[t] / sqrt(varz + 1e-5);
        g_cst[64 + t] = (float)(w * scz);
        g_cst[80 + t] = (float)((double)be_n1[t] + ((double)b_n1[t] - muz2) * scz);
    }
}

// ---------------- K4: t(ds) per element + moment partials ----------------
__global__ __launch_bounds__(512) void tstat_kernel(const float* __restrict__ W_n2,
                                                    const float* __restrict__ b_n2) {
    __shared__ float A[16], Bc[16], Wc[16];
    __shared__ double ws1[16], ws2[16];
    int t = threadIdx.x;
    if (t < 16) { A[t] = g_cst[64+t]; Bc[t] = g_cst[80+t]; Wc[t] = W_n2[t]; }
    __syncthreads();
    int e = blockIdx.x * 512 + t;
    float ds = g_dsv[e];
    float tv = b_n2[0];
#pragma unroll
    for (int i = 0; i < 16; i++)
        tv = fmaf(Wc[i], fmaxf(fmaf(A[i], ds, Bc[i]), 0.0f), tv);
    g_tbuf[e] = tv;
    double d1 = (double)tv, d2 = (double)tv * (double)tv;
#pragma unroll
    for (int o = 16; o > 0; o >>= 1) {
        d1 += __shfl_down_sync(FULLM, d1, o);
        d2 += __shfl_down_sync(FULLM, d2, o);
    }
    int lane = t & 31, warp = t >> 5;
    if (lane == 0) { ws1[warp] = d1; ws2[warp] = d2; }
    __syncthreads();
    if (t == 0) {
        double s1 = 0.0, s2 = 0.0;
#pragma unroll
        for (int w = 0; w < 16; w++) { s1 += ws1[w]; s2 += ws2[w]; }
        g_part2[blockIdx.x] = s1;
        g_part2[512 + blockIdx.x] = s2;
    }
}

// ---------------- K4b: finalize sigmoid-BN constants ----------------
__global__ void finalize2_kernel(const float* __restrict__ g_n2, const float* __restrict__ be_n2) {
    int lane = threadIdx.x;
    double s1 = 0.0, s2 = 0.0;
    for (int i = lane; i < 512; i += 32) { s1 += g_part2[i]; s2 += g_part2[512 + i]; }
#pragma unroll
    for (int o = 16; o > 0; o >>= 1) {
        s1 += __shfl_down_sync(FULLM, s1, o);
        s2 += __shfl_down_sync(FULLM, s2, o);
    }
    if (lane == 0) {
        double n = (double)NELEM;
        double mu = s1/n, var = s2/n - mu*mu;
        double S2 = (double)g_n2[0] / sqrt(var + 1e-5);
        g_cst[96] = (float)S2;
        g_cst[97] = (float)((double)be_n2[0] - mu * S2);
    }
}

// ------- K5: per-center mixed[d,m] = sum_k feat[d,k]*w[m,k] (f32x2 + sfeat[k][d]) -------
#define FST 68
__global__ __launch_bounds__(256) void mixed_kernel(const float* __restrict__ W_h,
                                                    const float* __restrict__ b_h) {
    int c = blockIdx.x;
    int b = c >> 11;
    int tid = threadIdx.x;
    __shared__ float sg[3][KS];
    __shared__ float sdsc[KS];
    __shared__ int   sidxs[KS];
    __shared__ float sfeat[KS][FST];
    if (tid < KS) {
        sg[0][tid] = g_gm[(size_t)(c*3 + 0)*KS + tid];
        sg[1][tid] = g_gm[(size_t)(c*3 + 1)*KS + tid];
        sg[2][tid] = g_gm[(size_t)(c*3 + 2)*KS + tid];
        sidxs[tid] = g_gidx[c*KS + tid];
        float tv = g_tbuf[c*KS + tid];
        sdsc[tid] = 1.0f / (1.0f + expf(-fmaf(g_cst[96], tv, g_cst[97])));
    }
    __syncthreads();
    int m = tid & 31;
    float w0 = W_h[m*3], w1 = W_h[m*3+1], w2 = W_h[m*3+2], bh = b_h[m];
    float sc = g_cst[m], sh = g_cst[32 + m];
    float wm[KS];
#pragma unroll
    for (int k = 0; k < KS; k++) {
        float a = fmaf(w2, sg[2][k], fmaf(w1, sg[1][k], fmaf(w0, sg[0][k], bh)));
        wm[k] = fmaxf(fmaf(sc, a, sh), 0.0f);
    }
    {
        int k = tid >> 3, q = tid & 7;
        int gi = sidxs[k];
        const float4* row = (const float4*)(g_ptsT + ((size_t)b*NPTS + gi)*DD);
        float4 v0 = row[q*2], v1 = row[q*2 + 1];
        float ds = sdsc[k];
        float4 o0, o1;
        o0.x = v0.x*ds; o0.y = v0.y*ds; o0.z = v0.z*ds; o0.w = v0.w*ds;
        o1.x = v1.x*ds; o1.y = v1.y*ds; o1.z = v1.z*ds; o1.w = v1.w*ds;
        *(float4*)&sfeat[k][q*8]     = o0;
        *(float4*)&sfeat[k][q*8 + 4] = o1;
    }
    __syncthreads();
    int dg = tid >> 5;
    u64 acc[4];
#pragma unroll
    for (int j = 0; j < 4; j++) acc[j] = 0ull;
#pragma unroll
    for (int k = 0; k < KS; k++) {
        float4 f0 = *(const float4*)&sfeat[k][dg*8];
        float4 f1 = *(const float4*)&sfeat[k][dg*8 + 4];
        u64 wk; PK2(wk, wm[k], wm[k]);
        u64 p0, p1, p2, p3;
        PK2(p0, f0.x, f0.y); PK2(p1, f0.z, f0.w);
        PK2(p2, f1.x, f1.y); PK2(p3, f1.z, f1.w);
        FMA2(acc[0], p0, wk);
        FMA2(acc[1], p1, wk);
        FMA2(acc[2], p2, wk);
        FMA2(acc[3], p3, wk);
    }
    float* outc = g_mixed + (size_t)c * 2048;
#pragma unroll
    for (int j = 0; j < 4; j++) {
        float lo, hi; UPK2(lo, hi, acc[j]);
        outc[(dg*8 + 2*j)*32 + m]     = lo;
        outc[(dg*8 + 2*j + 1)*32 + m] = hi;
    }
}

// ---- K6: Y = mixed @ Wout^T — BK=32, double-buffered, 1 bar/tile, fused Y-stats ----
#define BK2 32
#define GEMM_SMEM 49152   // As 2x(64x32) + Bs 2x(32x128) floats
__global__ __launch_bounds__(256) void gemm_kernel(const float* __restrict__ Wout) {
    extern __shared__ float gsm[];
    float* Asb[2] = { gsm,        gsm + 2048 };
    float* Bsb[2] = { gsm + 4096, gsm + 8192 };
    int m0 = blockIdx.x * 64;
    int tid = threadIdx.x;
    int tx = tid & 31, ty = tid >> 5;
    int ar = tid >> 2, aq = tid & 3;
    int bo = tid & 127, bh2 = tid >> 7;
    const float4* arow = (const float4*)(g_mixed + (size_t)(m0 + ar) * 2048);
    const float4* brow = (const float4*)(Wout + (size_t)bo * 2048);
    u64 acc01[8], acc23[8];
#pragma unroll
    for (int i = 0; i < 8; i++) { acc01[i] = 0ull; acc23[i] = 0ull; }
    float4 a0 = arow[aq*2], a1 = arow[aq*2 + 1];
    float4 bv0 = brow[bh2*4 + 0], bv1 = brow[bh2*4 + 1];
    float4 bv2 = brow[bh2*4 + 2], bv3 = brow[bh2*4 + 3];
    {
        float* A = Asb[0];
        *(float4*)(A + ar*BK2 + aq*8)     = a0;
        *(float4*)(A + ar*BK2 + aq*8 + 4) = a1;
        float* B = Bsb[0];
        int kb = bh2*16;
        B[(kb+ 0)*CO + bo] = bv0.x; B[(kb+ 1)*CO + bo] = bv0.y;
        B[(kb+ 2)*CO + bo] = bv0.z; B[(kb+ 3)*CO + bo] = bv0.w;
        B[(kb+ 4)*CO + bo] = bv1.x; B[(kb+ 5)*CO + bo] = bv1.y;
        B[(kb+ 6)*CO + bo] = bv1.z; B[(kb+ 7)*CO + bo] = bv1.w;
        B[(kb+ 8)*CO + bo] = bv2.x; B[(kb+ 9)*CO + bo] = bv2.y;
        B[(kb+10)*CO + bo] = bv2.z; B[(kb+11)*CO + bo] = bv2.w;
        B[(kb+12)*CO + bo] = bv3.x; B[(kb+13)*CO + bo] = bv3.y;
        B[(kb+14)*CO + bo] = bv3.z; B[(kb+15)*CO + bo] = bv3.w;
    }
    __syncthreads();
    const int NT = 2048 / BK2;   // 64 tiles
    for (int t = 0; t < NT; t++) {
        int cb = t & 1;
        if (t + 1 < NT) {
            int koff = (t + 1) * (BK2 / 4);
            a0  = arow[koff + aq*2];  a1  = arow[koff + aq*2 + 1];
            bv0 = brow[koff + bh2*4]; bv1 = brow[koff + bh2*4 + 1];
            bv2 = brow[koff + bh2*4 + 2]; bv3 = brow[koff + bh2*4 + 3];
        }
        const float* A = Asb[cb];
        const float* B = Bsb[cb];
#pragma unroll
        for (int kk = 0; kk < BK2; kk++) {
            float4 b4 = ((const float4*)(B + kk*CO))[tx];
            u64 b01, b23;
            PK2(b01, b4.x, b4.y);
            PK2(b23, b4.z, b4.w);
#pragma unroll
            for (int i = 0; i < 8; i++) {
                float a = A[(ty*8 + i)*BK2 + kk];
                u64 aa; PK2(aa, a, a);
                FMA2(acc01[i], aa, b01);
                FMA2(acc23[i], aa, b23);
            }
        }
        if (t + 1 < NT) {
            int nb = cb ^ 1;
            float* An = Asb[nb];
            *(float4*)(An + ar*BK2 + aq*8)     = a0;
            *(float4*)(An + ar*BK2 + aq*8 + 4) = a1;
            float* Bn = Bsb[nb];
            int kb = bh2*16;
            Bn[(kb+ 0)*CO + bo] = bv0.x; Bn[(kb+ 1)*CO + bo] = bv0.y;
            Bn[(kb+ 2)*CO + bo] = bv0.z; Bn[(kb+ 3)*CO + bo] = bv0.w;
            Bn[(kb+ 4)*CO + bo] = bv1.x; Bn[(kb+ 5)*CO + bo] = bv1.y;
            Bn[(kb+ 6)*CO + bo] = bv1.z; Bn[(kb+ 7)*CO + bo] = bv1.w;
            Bn[(kb+ 8)*CO + bo] = bv2.x; Bn[(kb+ 9)*CO + bo] = bv2.y;
            Bn[(kb+10)*CO + bo] = bv2.z; Bn[(kb+11)*CO + bo] = bv2.w;
            Bn[(kb+12)*CO + bo] = bv3.x; Bn[(kb+13)*CO + bo] = bv3.y;
            Bn[(kb+14)*CO + bo] = bv3.z; Bn[(kb+15)*CO + bo] = bv3.w;
        }
        __syncthreads();
    }
    double t1[4] = {0,0,0,0}, t2[4] = {0,0,0,0};
#pragma unroll
    for (int i = 0; i < 8; i++) {
        float4 r;
        UPK2(r.x, r.y, acc01[i]);
        UPK2(r.z, r.w, acc23[i]);
        ((float4*)(g_Y + (size_t)(m0 + ty*8 + i)*CO))[tx] = r;
        double v0 = r.x, v1 = r.y, v2 = r.z, v3 = r.w;
        t1[0] += v0; t2[0] += v0*v0;
        t1[1] += v1; t2[1] += v1*v1;
        t1[2] += v2; t2[2] += v2*v2;
        t1[3] += v3; t2[3] += v3*v3;
    }
    double* s1 = (double*)gsm;
    double* s2 = ((double*)gsm) + 1024;
#pragma unroll
    for (int j = 0; j < 4; j++) {
        s1[ty*CO + tx*4 + j] = t1[j];
        s2[ty*CO + tx*4 + j] = t2[j];
    }
    __syncthreads();
    if (tid < CO) {
        double u1 = 0.0, u2 = 0.0;
#pragma unroll
        for (int w = 0; w < 8; w++) { u1 += s1[w*CO + tid]; u2 += s2[w*CO + tid]; }
        g_ypart[blockIdx.x*256 + tid]       = u1;
        g_ypart[blockIdx.x*256 + 128 + tid] = u2;
    }
}

__global__ void finalize3_kernel(const float* __restrict__ g_out_p,
                                 const float* __restrict__ be_out_p) {
    int o = threadIdx.x;
    double s1 = 0.0, s2 = 0.0, s1b = 0.0, s2b = 0.0;
    for (int blk = 0; blk < 128; blk += 2) {
        s1  += g_ypart[blk*256 + o];
        s2  += g_ypart[blk*256 + 128 + o];
        s1b += g_ypart[(blk+1)*256 + o];
        s2b += g_ypart[(blk+1)*256 + 128 + o];
    }
    s1 += s1b; s2 += s2b;
    double mu = s1 / (double)NC, var = s2 / (double)NC - mu*mu;
    double sc = (double)g_out_p[o] / sqrt(var + 1e-5);
    g_ysc[o]       = (float)sc;
    g_ysc[128 + o] = (float)((double)be_out_p[o] - mu * sc);
}

// ---------------- K8: apply BN + transpose to (B, 128, S) ----------------
__global__ void apply_kernel(float* __restrict__ out) {
    __shared__ float tile[32][33];
    int b = blockIdx.z, o0 = blockIdx.y*32, s0 = blockIdx.x*32;
    int tx = threadIdx.x, ty = threadIdx.y;
    float sc = g_ysc[o0 + tx], sh = g_ysc[128 + o0 + tx];
#pragma unroll
    for (int k = 0; k < 4; k++) {
        int s = s0 + ty + 8*k;
        float v = g_Y[((size_t)(b*NS + s))*CO + o0 + tx];
        tile[ty + 8*k][tx] = fmaf(v, sc, sh);
    }
    __syncthreads();
#pragma unroll
    for (int k = 0; k < 4; k++) {
        int o = o0 + ty + 8*k;
        out[((size_t)(b*CO + o))*NS + s0 + tx] = tile[tx][ty + 8*k];
    }
}

// ---------------------------------- launch ----------------------------------
extern "C" void kernel_launch(void* const* d_in, const int* in_sizes, int n_in,
                              void* d_out, int out_size) {
    const float* xyz    = (const float*)d_in[0];
    const float* points = (const float*)d_in[1];
    const float* W_h    = (const float*)d_in[2];
    const float* b_h    = (const float*)d_in[3];
    const float* g_h    = (const float*)d_in[4];
    const float* be_h   = (const float*)d_in[5];
    const float* W_n1   = (const float*)d_in[6];
    const float* b_n1   = (const float*)d_in[7];
    const float* g_n1   = (const float*)d_in[8];
    const float* be_n1  = (const float*)d_in[9];
    const float* W_n2   = (const float*)d_in[10];
    const float* b_n2   = (const float*)d_in[11];
    const float* g_n2   = (const float*)d_in[12];
    const float* be_n2  = (const float*)d_in[13];
    const float* W_out  = (const float*)d_in[14];
    const float* g_out  = (const float*)d_in[16];
    const float* be_out = (const float*)d_in[17];
    const float* radius = (const float*)d_in[18];
    float* out = (float*)d_out;

    const int FPS_SMEM = 3 * NPTS * (int)sizeof(float);   // 96 KB
    static int s_attr_done = 0;
    if (!s_attr_done) {
        cudaFuncSetAttribute(fps_kernel, cudaFuncAttributeMaxDynamicSharedMemorySize, FPS_SMEM);
        cudaFuncSetAttribute(gemm_kernel, cudaFuncAttributeMaxDynamicSharedMemorySize, GEMM_SMEM);
        s_attr_done = 1;
    }

    dummy_kernel<<<1, 32>>>();
    transpose_kernel<<<dim3(NPTS/32, DD/32, BATCH), dim3(32, 8)>>>(points);
    dummy_kernel<<<1, 32>>>();
    fps_kernel<<<BATCH, 512, FPS_SMEM>>>(xyz);
    qball_kernel<<<NC/8, 256>>>(xyz, radius);
    finalize1_kernel<<<1, 384>>>(W_h, b_h, g_h, be_h, W_n1, b_n1, g_n1, be_n1);
    tstat_kernel<<<NELEM/512, 512>>>(W_n2, b_n2);
    finalize2_kernel<<<1, 32>>>(g_n2, be_n2);
    mixed_kernel<<<NC, 256>>>(W_h, b_h);
    gemm_kernel<<<NC/64, 256, GEMM_SMEM>>>(W_out);
    finalize3_kernel<<<1, 128>>>(g_out, be_out);
    apply_kernel<<<dim3(NS/32, CO/32, BATCH), dim3(32, 8)>>>(out);
}

// round 14
// speedup vs baseline: 1.0912x; 1.0912x over previous
#include <cuda_runtime.h>
#include <math.h>

#define BATCH 4
#define NPTS 8192
#define NS   2048
#define KS   32
#define DD   64
#define CO   128
#define NC   (BATCH*NS)          // 8192 centers
#define NELEM (NC*KS)            // 262144
#define FULLM 0xffffffffu

typedef unsigned long long u64;

// packed f32x2 helpers — each half is a bit-exact scalar .rn op (PTX ISA 8.6, sm_100+)
#define PK2(out, lo, hi) asm("mov.b64 %0, {%1, %2};" : "=l"(out) : "r"(__float_as_uint(lo)), "r"(__float_as_uint(hi)))
#define UPK2(lo, hi, in) do { unsigned _a,_b; asm("mov.b64 {%0, %1}, %2;" : "=r"(_a), "=r"(_b) : "l"(in)); lo=__uint_as_float(_a); hi=__uint_as_float(_b); } while(0)
#define ADD2(o, a, b) asm("add.rn.f32x2 %0, %1, %2;" : "=l"(o) : "l"(a), "l"(b))
#define MUL2(o, a, b) asm("mul.rn.f32x2 %0, %1, %2;" : "=l"(o) : "l"(a), "l"(b))
#define FMA2(acc, a, b) asm("fma.rn.f32x2 %0, %1, %2, %0;" : "+l"(acc) : "l"(a), "l"(b))

// ------------------- device scratch (no runtime allocation) -------------------
__device__ float  g_newxyz[NC*3];
__device__ int    g_gidx[NC*KS];
__device__ float  g_gm[NC*3*KS];          // [c][coord][k]
__device__ float  g_dsv[NC*KS];
__device__ float  g_tbuf[NC*KS];
__device__ double g_part1[1024*11];
__device__ double g_part2[1024];
__device__ float  g_cst[128];             // 0..31 scW, 32..63 shW, 64..79 A, 80..95 B, 96 S2, 97 T2
__device__ float  g_ptsT[(size_t)BATCH*NPTS*DD];     // 8 MB
__device__ float  g_mixed[(size_t)NC*2048];          // 64 MB
__device__ float  g_Y[(size_t)NC*CO];                // 4 MB
__device__ double g_ypart[256*256];
__device__ float  g_ysc[256];

// ---------------- dummy: shift qball_kernel into the ncu profiled slot ----------------
__global__ void dummy_kernel() {}

// ---------------- K0: transpose points (B,64,N) -> (B,N,64) ----------------
__global__ void transpose_kernel(const float* __restrict__ points) {
    __shared__ float tile[32][33];
    int b = blockIdx.z;
    int i0 = blockIdx.x * 32, d0 = blockIdx.y * 32;
    int tx = threadIdx.x, ty = threadIdx.y;   // 32 x 8
    const float* pb = points + (size_t)b * DD * NPTS;
    float* ob = g_ptsT + (size_t)b * NPTS * DD;
#pragma unroll
    for (int k = 0; k < 4; k++)
        tile[ty + k*8][tx] = pb[(size_t)(d0 + ty + k*8) * NPTS + i0 + tx];
    __syncthreads();
#pragma unroll
    for (int k = 0; k < 4; k++)
        ob[(size_t)(i0 + ty + k*8) * DD + d0 + tx] = tile[tx][ty + k*8];
}

// ---------------- K1: farthest point sampling (1 CTA / batch, 256 threads) ----------------
// Best-known config (R10): redux.sync warp max on float bits, redundant block
// max over 8 smem warp maxima, rescan + atomicMin only for block-max matches.
__global__ __launch_bounds__(256, 1) void fps_kernel(const float* __restrict__ xyz) {
    extern __shared__ float sm[];
    float* sx = sm;
    float* sy = sm + NPTS;
    float* sz = sm + 2*NPTS;
    __shared__ float wv[8];
    __shared__ int   sbest[2];
    int b = blockIdx.x;
    const float* xb = xyz + (size_t)b * 3 * NPTS;
    int t = threadIdx.x;
    int lane = t & 31, warp = t >> 5;
    int base = t * 32;
    u64 pxp[16], pyp[16], pzp[16];
    float dmin[32];
#pragma unroll
    for (int i = 0; i < 16; i++) {
        float x0 = xb[base + 2*i],          x1 = xb[base + 2*i + 1];
        float y0 = xb[NPTS + base + 2*i],   y1 = xb[NPTS + base + 2*i + 1];
        float z0 = xb[2*NPTS + base + 2*i], z1 = xb[2*NPTS + base + 2*i + 1];
        PK2(pxp[i], x0, x1); PK2(pyp[i], y0, y1); PK2(pzp[i], z0, z1);
        sx[base + 2*i] = x0; sx[base + 2*i + 1] = x1;
        sy[base + 2*i] = y0; sy[base + 2*i + 1] = y1;
        sz[base + 2*i] = z0; sz[base + 2*i + 1] = z1;
        dmin[2*i] = 10000000000.0f; dmin[2*i + 1] = 10000000000.0f;
    }
    if (t == 0) sbest[0] = 0;
    __syncthreads();
    float* outp = g_newxyz + (size_t)b * NS * 3;
    for (int s = 0; s < NS; s++) {
        int cur = sbest[s & 1];
        float cx = sx[cur], cy = sy[cur], cz = sz[cur];
        if (t == 0) {
            outp[s*3] = cx; outp[s*3+1] = cy; outp[s*3+2] = cz;
            sbest[(s + 1) & 1] = 0x7fffffff;   // reset next-step slot (pre-BAR1)
        }
        u64 ncx, ncy, ncz;
        PK2(ncx, -cx, -cx); PK2(ncy, -cy, -cy); PK2(ncz, -cz, -cz);
        float v = -1.0f;
#pragma unroll
        for (int i = 0; i < 16; i++) {
            u64 dx, dy, dz, xx, yy, zz, ss, dd;
            ADD2(dx, pxp[i], ncx);      // px + (-cx)  == px - cx exactly
            ADD2(dy, pyp[i], ncy);
            ADD2(dz, pzp[i], ncz);
            MUL2(xx, dx, dx);
            MUL2(yy, dy, dy);
            MUL2(zz, dz, dz);
            ADD2(ss, xx, yy);
            ADD2(dd, ss, zz);
            float d0, d1; UPK2(d0, d1, dd);
            float m0 = fminf(dmin[2*i],     d0); dmin[2*i]     = m0;
            float m1 = fminf(dmin[2*i + 1], d1); dmin[2*i + 1] = m1;
            v = fmaxf(v, fmaxf(m0, m1));
        }
        // warp max on bits (v >= 0 so the bit pattern is monotone in value)
        unsigned vbits = __float_as_uint(v);
        unsigned wbits;
        asm("redux.sync.max.u32 %0, %1, 0xffffffff;" : "=r"(wbits) : "r"(vbits));
        if (lane == 0) wv[warp] = __uint_as_float(wbits);
        __syncthreads();                       // BAR1: wv ready, reset visible
        float vblk = fmaxf(fmaxf(fmaxf(wv[0], wv[1]), fmaxf(wv[2], wv[3])),
                           fmaxf(fmaxf(wv[4], wv[5]), fmaxf(wv[6], wv[7])));
        if (v == vblk) {                       // ~1 thread per block
            int cand = base + 31;
#pragma unroll
            for (int j = 30; j >= 0; j--) if (dmin[j] == vblk) cand = base + j;
            atomicMin(&sbest[(s + 1) & 1], cand);
        }
        __syncthreads();                       // BAR2: sbest final
    }
}

// ------- K2: query ball + grouping + density + ds + moment partials -------
// Scan software-pipelined 4 blocks deep: 12 independent LDGs in flight
// (MLP ~12 vs 3 with the per-block break), break checked every 128 points.
// Extra blocks processed past cnt>=KS are discarded by the pos<KS guard, so
// the selected indices and all arithmetic are bit-identical to the reference.
__global__ __launch_bounds__(256) void qball_kernel(const float* __restrict__ xyz,
                                                    const float* __restrict__ radius) {
    int warp = threadIdx.x >> 5, lane = threadIdx.x & 31;
    int c = blockIdx.x * 8 + warp;
    int b = c >> 11;
    __shared__ int   sidx[8][KS];
    __shared__ float sred[8][11];
    const float* xb = xyz + (size_t)b * 3 * NPTS;
    float cx = g_newxyz[c*3], cy = g_newxyz[c*3+1], cz = g_newxyz[c*3+2];
    float cn2 = __fadd_rn(__fadd_rn(__fmul_rn(cx,cx), __fmul_rn(cy,cy)), __fmul_rn(cz,cz));
    float r = radius[0];
    float r2 = __fmul_rn(r, r);
    int cnt = 0;
    for (int nb = 0; nb < NPTS && cnt < KS; nb += 128) {
        float xs[4], ys[4], zs[4];
#pragma unroll
        for (int u = 0; u < 4; u++) {
            int i = nb + u*32 + lane;
            xs[u] = xb[i];
            ys[u] = xb[NPTS + i];
            zs[u] = xb[2*NPTS + i];
        }
#pragma unroll
        for (int u = 0; u < 4; u++) {
            int i = nb + u*32 + lane;
            float x = xs[u], y = ys[u], z = zs[u];
            float pn2 = __fadd_rn(__fadd_rn(__fmul_rn(x,x), __fmul_rn(y,y)), __fmul_rn(z,z));
            float dot = fmaf(cz, z, fmaf(cy, y, __fmul_rn(cx, x)));
            float sq  = __fsub_rn(__fadd_rn(cn2, pn2), __fmul_rn(2.0f, dot));
            bool in = !(sq > r2);
            unsigned msk = __ballot_sync(FULLM, in);
            if (in) {
                int pos = cnt + __popc(msk & ((1u << lane) - 1u));
                if (pos < KS) sidx[warp][pos] = i;
            }
            cnt += __popc(msk);
        }
    }
    __syncwarp();
    int first = sidx[warp][0];
    __syncwarp();
    if (lane >= cnt) sidx[warp][lane] = first;
    __syncwarp();
    int gi = sidx[warp][lane];
    float gx, gy, gz;
    if (lane == 0) { gx = 0.f; gy = 0.f; gz = 0.f; }
    else { gx = xb[gi]; gy = xb[NPTS + gi]; gz = xb[2*NPTS + gi]; }
    float den = __fadd_rn(__fadd_rn(gx, gy), gz);
    if (den < 1e-10f) den = 1e-10f;
    float inv = 1.0f / den;
    float mx = inv;
#pragma unroll
    for (int o = 16; o > 0; o >>= 1) mx = fmaxf(mx, __shfl_xor_sync(FULLM, mx, o));
    float dsv = inv / mx;
    g_gidx[c*KS + lane] = gi;
    g_gm[(size_t)(c*3 + 0)*KS + lane] = gx;
    g_gm[(size_t)(c*3 + 1)*KS + lane] = gy;
    g_gm[(size_t)(c*3 + 2)*KS + lane] = gz;
    g_dsv[c*KS + lane] = dsv;
    float q[11] = {gx, gy, gz, gx*gx, gx*gy, gx*gz, gy*gy, gy*gz, gz*gz, dsv, dsv*dsv};
#pragma unroll
    for (int qi = 0; qi < 11; qi++) {
        float vv = q[qi];
#pragma unroll
        for (int o = 16; o > 0; o >>= 1) vv += __shfl_xor_sync(FULLM, vv, o);
        if (lane == 0) sred[warp][qi] = vv;
    }
    __syncthreads();
    if (threadIdx.x < 11) {
        double ssum = 0.0;
#pragma unroll
        for (int w = 0; w < 8; w++) ssum += (double)sred[w][threadIdx.x];
        g_part1[blockIdx.x * 11 + threadIdx.x] = ssum;
    }
}

// ---------------- K3: finalize BN(w) and BN(n1) constants (warp-parallel) ----------------
__global__ void finalize1_kernel(const float* __restrict__ W_h, const float* __restrict__ b_h,
                                 const float* __restrict__ g_h, const float* __restrict__ be_h,
                                 const float* __restrict__ W_n1, const float* __restrict__ b_n1,
                                 const float* __restrict__ g_n1, const float* __restrict__ be_n1) {
    __shared__ double S[11];
    int t = threadIdx.x;          // 384 threads, 12 warps
    int warp = t >> 5, lane = t & 31;
    if (warp < 11) {
        double s = 0.0;
        for (int i = lane; i < 1024; i += 32) s += g_part1[i*11 + warp];
#pragma unroll
        for (int o = 16; o > 0; o >>= 1) s += __shfl_down_sync(FULLM, s, o);
        if (lane == 0) S[warp] = s;
    }
    __syncthreads();
    const double n = (double)NELEM;
    if (t < 32) {
        double mux = S[0]/n, muy = S[1]/n, muz = S[2]/n;
        double cxx = S[3]/n - mux*mux, cxy = S[4]/n - mux*muy, cxz = S[5]/n - mux*muz;
        double cyy = S[6]/n - muy*muy, cyz = S[7]/n - muy*muz, czz = S[8]/n - muz*muz;
        double w0 = W_h[t*3], w1 = W_h[t*3+1], w2 = W_h[t*3+2];
        double mua = w0*mux + w1*muy + w2*muz + (double)b_h[t];
        double var = w0*w0*cxx + w1*w1*cyy + w2*w2*czz
                   + 2.0*(w0*w1*cxy + w0*w2*cxz + w1*w2*cyz);
        double sc = (double)g_h[t] / sqrt(var + 1e-5);
        g_cst[t]      = (float)sc;
        g_cst[32 + t] = (float)((double)be_h[t] - mua * sc);
    }
    if (t < 16) {
        double mud  = S[9]/n;
        double vard = S[10]/n - mud*mud;
        double w = W_n1[t];
        double muz2 = w*mud + (double)b_n1[t];
        double varz = w*w*vard;
        double scz = (double)g_n1[t] / sqrt(varz + 1e-5);
        g_cst[64 + t] = (float)(w * scz);
        g_cst[80 + t] = (float)((double)be_n1[t] + ((double)b_n1[t] - muz2) * scz);
    }
}

// ---------------- K4: t(ds) per element + moment partials ----------------
__global__ __launch_bounds__(512) void tstat_kernel(const float* __restrict__ W_n2,
                                                    const float* __restrict__ b_n2) {
    __shared__ float A[16], Bc[16], Wc[16];
    __shared__ double ws1[16], ws2[16];
    int t = threadIdx.x;
    if (t < 16) { A[t] = g_cst[64+t]; Bc[t] = g_cst[80+t]; Wc[t] = W_n2[t]; }
    __syncthreads();
    int e = blockIdx.x * 512 + t;
    float ds = g_dsv[e];
    float tv = b_n2[0];
#pragma unroll
    for (int i = 0; i < 16; i++)
        tv = fmaf(Wc[i], fmaxf(fmaf(A[i], ds, Bc[i]), 0.0f), tv);
    g_tbuf[e] = tv;
    double d1 = (double)tv, d2 = (double)tv * (double)tv;
#pragma unroll
    for (int o = 16; o > 0; o >>= 1) {
        d1 += __shfl_down_sync(FULLM, d1, o);
        d2 += __shfl_down_sync(FULLM, d2, o);
    }
    int lane = t & 31, warp = t >> 5;
    if (lane == 0) { ws1[warp] = d1; ws2[warp] = d2; }
    __syncthreads();
    if (t == 0) {
        double s1 = 0.0, s2 = 0.0;
#pragma unroll
        for (int w = 0; w < 16; w++) { s1 += ws1[w]; s2 += ws2[w]; }
        g_part2[blockIdx.x] = s1;
        g_part2[512 + blockIdx.x] = s2;
    }
}

// ---------------- K4b: finalize sigmoid-BN constants ----------------
__global__ void finalize2_kernel(const float* __restrict__ g_n2, const float* __restrict__ be_n2) {
    int lane = threadIdx.x;
    double s1 = 0.0, s2 = 0.0;
    for (int i = lane; i < 512; i += 32) { s1 += g_part2[i]; s2 += g_part2[512 + i]; }
#pragma unroll
    for (int o = 16; o > 0; o >>= 1) {
        s1 += __shfl_down_sync(FULLM, s1, o);
        s2 += __shfl_down_sync(FULLM, s2, o);
    }
    if (lane == 0) {
        double n = (double)NELEM;
        double mu = s1/n, var = s2/n - mu*mu;
        double S2 = (double)g_n2[0] / sqrt(var + 1e-5);
        g_cst[96] = (float)S2;
        g_cst[97] = (float)((double)be_n2[0] - mu * S2);
    }
}

// ------- K5: per-center mixed[d,m] = sum_k feat[d,k]*w[m,k] (f32x2 + sfeat[k][d]) -------
#define FST 68
__global__ __launch_bounds__(256) void mixed_kernel(const float* __restrict__ W_h,
                                                    const float* __restrict__ b_h) {
    int c = blockIdx.x;
    int b = c >> 11;
    int tid = threadIdx.x;
    __shared__ float sg[3][KS];
    __shared__ float sdsc[KS];
    __shared__ int   sidxs[KS];
    __shared__ float sfeat[KS][FST];
    if (tid < KS) {
        sg[0][tid] = g_gm[(size_t)(c*3 + 0)*KS + tid];
        sg[1][tid] = g_gm[(size_t)(c*3 + 1)*KS + tid];
        sg[2][tid] = g_gm[(size_t)(c*3 + 2)*KS + tid];
        sidxs[tid] = g_gidx[c*KS + tid];
        float tv = g_tbuf[c*KS + tid];
        sdsc[tid] = 1.0f / (1.0f + expf(-fmaf(g_cst[96], tv, g_cst[97])));
    }
    __syncthreads();
    int m = tid & 31;
    float w0 = W_h[m*3], w1 = W_h[m*3+1], w2 = W_h[m*3+2], bh = b_h[m];
    float sc = g_cst[m], sh = g_cst[32 + m];
    float wm[KS];
#pragma unroll
    for (int k = 0; k < KS; k++) {
        float a = fmaf(w2, sg[2][k], fmaf(w1, sg[1][k], fmaf(w0, sg[0][k], bh)));
        wm[k] = fmaxf(fmaf(sc, a, sh), 0.0f);
    }
    {
        int k = tid >> 3, q = tid & 7;
        int gi = sidxs[k];
        const float4* row = (const float4*)(g_ptsT + ((size_t)b*NPTS + gi)*DD);
        float4 v0 = row[q*2], v1 = row[q*2 + 1];
        float ds = sdsc[k];
        float4 o0, o1;
        o0.x = v0.x*ds; o0.y = v0.y*ds; o0.z = v0.z*ds; o0.w = v0.w*ds;
        o1.x = v1.x*ds; o1.y = v1.y*ds; o1.z = v1.z*ds; o1.w = v1.w*ds;
        *(float4*)&sfeat[k][q*8]     = o0;
        *(float4*)&sfeat[k][q*8 + 4] = o1;
    }
    __syncthreads();
    int dg = tid >> 5;
    u64 acc[4];
#pragma unroll
    for (int j = 0; j < 4; j++) acc[j] = 0ull;
#pragma unroll
    for (int k = 0; k < KS; k++) {
        float4 f0 = *(const float4*)&sfeat[k][dg*8];
        float4 f1 = *(const float4*)&sfeat[k][dg*8 + 4];
        u64 wk; PK2(wk, wm[k], wm[k]);
        u64 p0, p1, p2, p3;
        PK2(p0, f0.x, f0.y); PK2(p1, f0.z, f0.w);
        PK2(p2, f1.x, f1.y); PK2(p3, f1.z, f1.w);
        FMA2(acc[0], p0, wk);
        FMA2(acc[1], p1, wk);
        FMA2(acc[2], p2, wk);
        FMA2(acc[3], p3, wk);
    }
    float* outc = g_mixed + (size_t)c * 2048;
#pragma unroll
    for (int j = 0; j < 4; j++) {
        float lo, hi; UPK2(lo, hi, acc[j]);
        outc[(dg*8 + 2*j)*32 + m]     = lo;
        outc[(dg*8 + 2*j + 1)*32 + m] = hi;
    }
}

// ---- K6: Y = mixed @ Wout^T — BK=32, double-buffered, 1 bar/tile, fused Y-stats ----
#define BK2 32
#define GEMM_SMEM 49152   // As 2x(64x32) + Bs 2x(32x128) floats
__global__ __launch_bounds__(256) void gemm_kernel(const float* __restrict__ Wout) {
    extern __shared__ float gsm[];
    float* Asb[2] = { gsm,        gsm + 2048 };
    float* Bsb[2] = { gsm + 4096, gsm + 8192 };
    int m0 = blockIdx.x * 64;
    int tid = threadIdx.x;
    int tx = tid & 31, ty = tid >> 5;
    int ar = tid >> 2, aq = tid & 3;
    int bo = tid & 127, bh2 = tid >> 7;
    const float4* arow = (const float4*)(g_mixed + (size_t)(m0 + ar) * 2048);
    const float4* brow = (const float4*)(Wout + (size_t)bo * 2048);
    u64 acc01[8], acc23[8];
#pragma unroll
    for (int i = 0; i < 8; i++) { acc01[i] = 0ull; acc23[i] = 0ull; }
    float4 a0 = arow[aq*2], a1 = arow[aq*2 + 1];
    float4 bv0 = brow[bh2*4 + 0], bv1 = brow[bh2*4 + 1];
    float4 bv2 = brow[bh2*4 + 2], bv3 = brow[bh2*4 + 3];
    {
        float* A = Asb[0];
        *(float4*)(A + ar*BK2 + aq*8)     = a0;
        *(float4*)(A + ar*BK2 + aq*8 + 4) = a1;
        float* B = Bsb[0];
        int kb = bh2*16;
        B[(kb+ 0)*CO + bo] = bv0.x; B[(kb+ 1)*CO + bo] = bv0.y;
        B[(kb+ 2)*CO + bo] = bv0.z; B[(kb+ 3)*CO + bo] = bv0.w;
        B[(kb+ 4)*CO + bo] = bv1.x; B[(kb+ 5)*CO + bo] = bv1.y;
        B[(kb+ 6)*CO + bo] = bv1.z; B[(kb+ 7)*CO + bo] = bv1.w;
        B[(kb+ 8)*CO + bo] = bv2.x; B[(kb+ 9)*CO + bo] = bv2.y;
        B[(kb+10)*CO + bo] = bv2.z; B[(kb+11)*CO + bo] = bv2.w;
        B[(kb+12)*CO + bo] = bv3.x; B[(kb+13)*CO + bo] = bv3.y;
        B[(kb+14)*CO + bo] = bv3.z; B[(kb+15)*CO + bo] = bv3.w;
    }
    __syncthreads();
    const int NT = 2048 / BK2;   // 64 tiles
    for (int t = 0; t < NT; t++) {
        int cb = t & 1;
        if (t + 1 < NT) {
            int koff = (t + 1) * (BK2 / 4);
            a0  = arow[koff + aq*2];  a1  = arow[koff + aq*2 + 1];
            bv0 = brow[koff + bh2*4]; bv1 = brow[koff + bh2*4 + 1];
            bv2 = brow[koff + bh2*4 + 2]; bv3 = brow[koff + bh2*4 + 3];
        }
        const float* A = Asb[cb];
        const float* B = Bsb[cb];
#pragma unroll
        for (int kk = 0; kk < BK2; kk++) {
            float4 b4 = ((const float4*)(B + kk*CO))[tx];
            u64 b01, b23;
            PK2(b01, b4.x, b4.y);
            PK2(b23, b4.z, b4.w);
#pragma unroll
            for (int i = 0; i < 8; i++) {
                float a = A[(ty*8 + i)*BK2 + kk];
                u64 aa; PK2(aa, a, a);
                FMA2(acc01[i], aa, b01);
                FMA2(acc23[i], aa, b23);
            }
        }
        if (t + 1 < NT) {
            int nb = cb ^ 1;
            float* An = Asb[nb];
            *(float4*)(An + ar*BK2 + aq*8)     = a0;
            *(float4*)(An + ar*BK2 + aq*8 + 4) = a1;
            float* Bn = Bsb[nb];
            int kb = bh2*16;
            Bn[(kb+ 0)*CO + bo] = bv0.x; Bn[(kb+ 1)*CO + bo] = bv0.y;
            Bn[(kb+ 2)*CO + bo] = bv0.z; Bn[(kb+ 3)*CO + bo] = bv0.w;
            Bn[(kb+ 4)*CO + bo] = bv1.x; Bn[(kb+ 5)*CO + bo] = bv1.y;
            Bn[(kb+ 6)*CO + bo] = bv1.z; Bn[(kb+ 7)*CO + bo] = bv1.w;
            Bn[(kb+ 8)*CO + bo] = bv2.x; Bn[(kb+ 9)*CO + bo] = bv2.y;
            Bn[(kb+10)*CO + bo] = bv2.z; Bn[(kb+11)*CO + bo] = bv2.w;
            Bn[(kb+12)*CO + bo] = bv3.x; Bn[(kb+13)*CO + bo] = bv3.y;
            Bn[(kb+14)*CO + bo] = bv3.z; Bn[(kb+15)*CO + bo] = bv3.w;
        }
        __syncthreads();
    }
    double t1[4] = {0,0,0,0}, t2[4] = {0,0,0,0};
#pragma unroll
    for (int i = 0; i < 8; i++) {
        float4 r;
        UPK2(r.x, r.y, acc01[i]);
        UPK2(r.z, r.w, acc23[i]);
        ((float4*)(g_Y + (size_t)(m0 + ty*8 + i)*CO))[tx] = r;
        double v0 = r.x, v1 = r.y, v2 = r.z, v3 = r.w;
        t1[0] += v0; t2[0] += v0*v0;
        t1[1] += v1; t2[1] += v1*v1;
        t1[2] += v2; t2[2] += v2*v2;
        t1[3] += v3; t2[3] += v3*v3;
    }
    double* s1 = (double*)gsm;
    double* s2 = ((double*)gsm) + 1024;
#pragma unroll
    for (int j = 0; j < 4; j++) {
        s1[ty*CO + tx*4 + j] = t1[j];
        s2[ty*CO + tx*4 + j] = t2[j];
    }
    __syncthreads();
    if (tid < CO) {
        double u1 = 0.0, u2 = 0.0;
#pragma unroll
        for (int w = 0; w < 8; w++) { u1 += s1[w*CO + tid]; u2 += s2[w*CO + tid]; }
        g_ypart[blockIdx.x*256 + tid]       = u1;
        g_ypart[blockIdx.x*256 + 128 + tid] = u2;
    }
}

__global__ void finalize3_kernel(const float* __restrict__ g_out_p,
                                 const float* __restrict__ be_out_p) {
    int o = threadIdx.x;
    double s1 = 0.0, s2 = 0.0, s1b = 0.0, s2b = 0.0;
    for (int blk = 0; blk < 128; blk += 2) {
        s1  += g_ypart[blk*256 + o];
        s2  += g_ypart[blk*256 + 128 + o];
        s1b += g_ypart[(blk+1)*256 + o];
        s2b += g_ypart[(blk+1)*256 + 128 + o];
    }
    s1 += s1b; s2 += s2b;
    double mu = s1 / (double)NC, var = s2 / (double)NC - mu*mu;
    double sc = (double)g_out_p[o] / sqrt(var + 1e-5);
    g_ysc[o]       = (float)sc;
    g_ysc[128 + o] = (float)((double)be_out_p[o] - mu * sc);
}

// ---------------- K8: apply BN + transpose to (B, 128, S) ----------------
__global__ void apply_kernel(float* __restrict__ out) {
    __shared__ float tile[32][33];
    int b = blockIdx.z, o0 = blockIdx.y*32, s0 = blockIdx.x*32;
    int tx = threadIdx.x, ty = threadIdx.y;
    float sc = g_ysc[o0 + tx], sh = g_ysc[128 + o0 + tx];
#pragma unroll
    for (int k = 0; k < 4; k++) {
        int s = s0 + ty + 8*k;
        float v = g_Y[((size_t)(b*NS + s))*CO + o0 + tx];
        tile[ty + 8*k][tx] = fmaf(v, sc, sh);
    }
    __syncthreads();
#pragma unroll
    for (int k = 0; k < 4; k++) {
        int o = o0 + ty + 8*k;
        out[((size_t)(b*CO + o))*NS + s0 + tx] = tile[tx][ty + 8*k];
    }
}

// ---------------------------------- launch ----------------------------------
extern "C" void kernel_launch(void* const* d_in, const int* in_sizes, int n_in,
                              void* d_out, int out_size) {
    const float* xyz    = (const float*)d_in[0];
    const float* points = (const float*)d_in[1];
    const float* W_h    = (const float*)d_in[2];
    const float* b_h    = (const float*)d_in[3];
    const float* g_h    = (const float*)d_in[4];
    const float* be_h   = (const float*)d_in[5];
    const float* W_n1   = (const float*)d_in[6];
    const float* b_n1   = (const float*)d_in[7];
    const float* g_n1   = (const float*)d_in[8];
    const float* be_n1  = (const float*)d_in[9];
    const float* W_n2   = (const float*)d_in[10];
    const float* b_n2   = (const float*)d_in[11];
    const float* g_n2   = (const float*)d_in[12];
    const float* be_n2  = (const float*)d_in[13];
    const float* W_out  = (const float*)d_in[14];
    const float* g_out  = (const float*)d_in[16];
    const float* be_out = (const float*)d_in[17];
    const float* radius = (const float*)d_in[18];
    float* out = (float*)d_out;

    const int FPS_SMEM = 3 * NPTS * (int)sizeof(float);   // 96 KB
    static int s_attr_done = 0;
    if (!s_attr_done) {
        cudaFuncSetAttribute(fps_kernel, cudaFuncAttributeMaxDynamicSharedMemorySize, FPS_SMEM);
        cudaFuncSetAttribute(gemm_kernel, cudaFuncAttributeMaxDynamicSharedMemorySize, GEMM_SMEM);
        s_attr_done = 1;
    }

    dummy_kernel<<<1, 32>>>();                 // launch idx 0 -> qball lands at idx 3
    transpose_kernel<<<dim3(NPTS/32, DD/32, BATCH), dim3(32, 8)>>>(points);
    fps_kernel<<<BATCH, 256, FPS_SMEM>>>(xyz);
    qball_kernel<<<NC/8, 256>>>(xyz, radius);
    finalize1_kernel<<<1, 384>>>(W_h, b_h, g_h, be_h, W_n1, b_n1, g_n1, be_n1);
    tstat_kernel<<<NELEM/512, 512>>>(W_n2, b_n2);
    finalize2_kernel<<<1, 32>>>(g_n2, be_n2);
    mixed_kernel<<<NC, 256>>>(W_h, b_h);
    gemm_kernel<<<NC/64, 256, GEMM_SMEM>>>(W_out);
    finalize3_kernel<<<1, 128>>>(g_out, be_out);
    apply_kernel<<<dim3(NS/32, CO/32, BATCH), dim3(32, 8)>>>(out);
}